// round 9
// baseline (speedup 1.0000x reference)
#include <cuda_runtime.h>
#include <cstdint>

#define BATCH 64
#define TIN   128
#define FIN   64
#define HID   512
#define G4    2048
#define TOUTN 64
#define KLIN  32768
#define NLIN  4096

#define KSPLIT 4
#define KPER   (KLIN / KSPLIT)
#define LCHUNK 64
#define LNCH   (KPER / LCHUNK)

#define NBLK_L 64
#define AP 132
// lstm smem offsets (u32 units)
#define AHI_OFF 32768
#define ALO_OFF (AHI_OFF + 8448)
#define CSM_OFF (ALO_OFF + 8448)
#define RED_OFF (CSM_OFF + 2304)
#define DSMW    (RED_OFF + 2048)   // 54016 u32 = 216064 B

__device__ float g_xT[TIN * BATCH * FIN];
__device__ float g_pre1[TIN * BATCH * G4];
__device__ float g_pre2[BATCH * G4];
__device__ float g_hA[BATCH * HID];
__device__ float g_hB[BATCH * HID];
__device__ uint32_t g_hAhi[BATCH * HID];
__device__ uint32_t g_hAlo[BATCH * HID];
__device__ uint32_t g_hBhi[BATCH * HID];
__device__ uint32_t g_hBlo[BATCH * HID];
__device__ float g_c[BATCH * HID];
__device__ float g_seq[BATCH * KLIN];
__device__ float g_part[KSPLIT * BATCH * NLIN];
__device__ unsigned g_ctr[8];

__device__ __forceinline__ uint32_t f2tf(float f) {
    uint32_t u;
    asm("cvt.rna.tf32.f32 %0, %1;" : "=r"(u) : "f"(f));
    return u;
}
__device__ __forceinline__ void mma_tf32(float* c, const uint32_t* a, const uint32_t* b) {
    asm volatile(
        "mma.sync.aligned.m16n8k8.row.col.f32.tf32.tf32.f32 "
        "{%0,%1,%2,%3}, {%4,%5,%6,%7}, {%8,%9}, {%0,%1,%2,%3};"
        : "+f"(c[0]), "+f"(c[1]), "+f"(c[2]), "+f"(c[3])
        : "r"(a[0]), "r"(a[1]), "r"(a[2]), "r"(a[3]), "r"(b[0]), "r"(b[1]));
}

// ---------------- small kernels ----------------
__global__ void k_xt(const float* __restrict__ x) {
    int i = blockIdx.x * 256 + threadIdx.x;
    if (i < TIN * BATCH * FIN) {
        int k = i & 63, r = i >> 6;
        int t = r >> 6, b = r & 63;
        g_xT[i] = x[(b * TIN + t) * FIN + k];
    }
}
__global__ void k_init() {
    int i = blockIdx.x * 256 + threadIdx.x;
    if (i < BATCH * HID) {
        g_hA[i] = 0.0f;
        g_hAhi[i] = 0u;
        g_hAlo[i] = 0u;
    }
    if (blockIdx.x == 0 && threadIdx.x < 8) g_ctr[threadIdx.x] = 0u;
}
__global__ void k_zero() {
    if (threadIdx.x < 8) g_ctr[threadIdx.x] = 0u;
}
__global__ void k_combine(const float* __restrict__ blin, float* __restrict__ out) {
    int i = blockIdx.x * 256 + threadIdx.x;
    if (i < BATCH * NLIN) {
        int b = i >> 12, m = i & 4095;
        float s = blin[m];
#pragma unroll
        for (int ks = 0; ks < KSPLIT; ++ks)
            s += g_part[((size_t)ks * BATCH + b) * NLIN + m];
        out[i] = s;
    }
}

// ---------------- fp32 SIMT GEMM (pre-projections, proven) ----------------
__device__ __forceinline__ void gemm64_core(
    const float* __restrict__ A, int lda,
    const float* __restrict__ W, int ldw,
    float* __restrict__ C, int ldc, int kcount,
    const float* __restrict__ bias1, const float* __restrict__ bias2)
{
    __shared__ __align__(16) float As[2][32 * 68];
    __shared__ __align__(16) float Ws[2][32 * 68];
    const int tid = threadIdx.x;
    const int n0 = blockIdx.x * 64;
    const int mbase = blockIdx.z * 64;
    const int b0 = (tid & 15) * 4, nt = (tid >> 4) * 4;
    float acc[4][4];
#pragma unroll
    for (int i = 0; i < 4; ++i)
#pragma unroll
        for (int j = 0; j < 4; ++j) acc[i][j] = 0.0f;
    const int ntiles = kcount >> 5;
#pragma unroll
    for (int e = 0; e < 8; ++e) {
        int idx = tid + e * 256, m = idx >> 5, k = idx & 31;
        As[0][k * 68 + m] = A[(size_t)(mbase + m) * lda + k];
        Ws[0][k * 68 + m] = W[(size_t)(n0 + m) * ldw + k];
    }
    __syncthreads();
    for (int kt = 0; kt < ntiles; ++kt) {
        float pfA[8], pfW[8];
        const bool more = (kt + 1 < ntiles);
        if (more) {
            int ko = (kt + 1) << 5;
#pragma unroll
            for (int e = 0; e < 8; ++e) {
                int idx = tid + e * 256, m = idx >> 5, k = idx & 31;
                pfA[e] = A[(size_t)(mbase + m) * lda + ko + k];
                pfW[e] = W[(size_t)(n0 + m) * ldw + ko + k];
            }
        }
        const float* as = As[kt & 1];
        const float* wz = Ws[kt & 1];
#pragma unroll
        for (int k = 0; k < 32; ++k) {
            float4 av = *(const float4*)(as + k * 68 + b0);
            float4 wv = *(const float4*)(wz + k * 68 + nt);
            float aa[4] = {av.x, av.y, av.z, av.w};
            float ww[4] = {wv.x, wv.y, wv.z, wv.w};
#pragma unroll
            for (int i = 0; i < 4; ++i)
#pragma unroll
                for (int j = 0; j < 4; ++j)
                    acc[i][j] = fmaf(aa[i], ww[j], acc[i][j]);
        }
        if (more) {
            float* dA = As[(kt + 1) & 1];
            float* dW = Ws[(kt + 1) & 1];
#pragma unroll
            for (int e = 0; e < 8; ++e) {
                int idx = tid + e * 256, m = idx >> 5, k = idx & 31;
                dA[k * 68 + m] = pfA[e];
                dW[k * 68 + m] = pfW[e];
            }
        }
        __syncthreads();
    }
#pragma unroll
    for (int i = 0; i < 4; ++i) {
        int m = mbase + b0 + i;
#pragma unroll
        for (int j = 0; j < 4; ++j) {
            int n = n0 + nt + j;
            C[(size_t)m * ldc + n] = acc[i][j] + bias1[n] + bias2[n];
        }
    }
}
__global__ void __launch_bounds__(256) k_pre1(const float* __restrict__ W,
                                              const float* __restrict__ b1,
                                              const float* __restrict__ b2) {
    gemm64_core(g_xT, FIN, W, FIN, g_pre1, G4, FIN, b1, b2);
}
__global__ void __launch_bounds__(256) k_pre2(const float* __restrict__ W,
                                              const float* __restrict__ b1,
                                              const float* __restrict__ b2) {
    gemm64_core(g_hA, HID, W, HID, g_pre2, G4, HID, b1, b2);
}

// ---------------- tf32 mma.sync linear (proven in R7/R8) ----------------
__global__ void __launch_bounds__(256, 1) k_lin_mma(const float* __restrict__ Wl) {
    extern __shared__ __align__(16) uint32_t lsm[];
    const int tid = threadIdx.x, wid = tid >> 5, lane = tid & 31;
    const int gid = lane >> 2, tig = lane & 3;
    const int m0 = blockIdx.x * 128;
    const int ks = blockIdx.y;
    const int k0b = ks * KPER;

    float acc[4][2][4];
#pragma unroll
    for (int mt = 0; mt < 4; ++mt)
#pragma unroll
        for (int nt = 0; nt < 2; ++nt)
#pragma unroll
            for (int r = 0; r < 4; ++r) acc[mt][nt][r] = 0.0f;
    {
        uint32_t* A0 = lsm;
        uint32_t* W0 = lsm + 4352;
#pragma unroll
        for (int e = 0; e < 4; ++e) {
            int idx = tid + e * 256, row = idx >> 4, c4 = idx & 15;
            float4 v = *(const float4*)(g_seq + (size_t)row * KLIN + k0b + c4 * 4);
            uint32_t* d = A0 + row * 68 + c4 * 4;
            d[0] = f2tf(v.x); d[1] = f2tf(v.y); d[2] = f2tf(v.z); d[3] = f2tf(v.w);
        }
#pragma unroll
        for (int e = 0; e < 8; ++e) {
            int idx = tid + e * 256, row = idx >> 4, c4 = idx & 15;
            float4 v = *(const float4*)(Wl + (size_t)(m0 + row) * KLIN + k0b + c4 * 4);
            uint32_t* d = W0 + row * 68 + c4 * 4;
            d[0] = f2tf(v.x); d[1] = f2tf(v.y); d[2] = f2tf(v.z); d[3] = f2tf(v.w);
        }
    }
    __syncthreads();

    for (int ch = 0; ch < LNCH; ++ch) {
        const int buf = ch & 1;
        const bool more = (ch + 1 < LNCH);
        float4 fa[4], fw[8];
        if (more) {
            int k0 = k0b + (ch + 1) * LCHUNK;
#pragma unroll
            for (int e = 0; e < 4; ++e) {
                int idx = tid + e * 256, row = idx >> 4, c4 = idx & 15;
                fa[e] = *(const float4*)(g_seq + (size_t)row * KLIN + k0 + c4 * 4);
            }
#pragma unroll
            for (int e = 0; e < 8; ++e) {
                int idx = tid + e * 256, row = idx >> 4, c4 = idx & 15;
                fw[e] = *(const float4*)(Wl + (size_t)(m0 + row) * KLIN + k0 + c4 * 4);
            }
        }
        const uint32_t* As = lsm + buf * 13056;
        const uint32_t* Ws = lsm + buf * 13056 + 4352;
#pragma unroll
        for (int kk = 0; kk < 8; ++kk) {
            uint32_t a[4][4], b[2][2];
#pragma unroll
            for (int mt = 0; mt < 4; ++mt) {
                const uint32_t* ap = As + (mt * 16 + gid) * 68 + kk * 8 + tig;
                a[mt][0] = ap[0];
                a[mt][1] = ap[8 * 68];
                a[mt][2] = ap[4];
                a[mt][3] = ap[8 * 68 + 4];
            }
#pragma unroll
            for (int nt = 0; nt < 2; ++nt) {
                const uint32_t* bp = Ws + (wid * 16 + nt * 8 + gid) * 68 + kk * 8 + tig;
                b[nt][0] = bp[0];
                b[nt][1] = bp[4];
            }
#pragma unroll
            for (int mt = 0; mt < 4; ++mt)
#pragma unroll
                for (int nt = 0; nt < 2; ++nt)
                    mma_tf32(acc[mt][nt], a[mt], b[nt]);
        }
        if (more) {
            uint32_t* A1 = lsm + (buf ^ 1) * 13056;
            uint32_t* W1 = A1 + 4352;
#pragma unroll
            for (int e = 0; e < 4; ++e) {
                int idx = tid + e * 256, row = idx >> 4, c4 = idx & 15;
                uint32_t* d = A1 + row * 68 + c4 * 4;
                d[0] = f2tf(fa[e].x); d[1] = f2tf(fa[e].y);
                d[2] = f2tf(fa[e].z); d[3] = f2tf(fa[e].w);
            }
#pragma unroll
            for (int e = 0; e < 8; ++e) {
                int idx = tid + e * 256, row = idx >> 4, c4 = idx & 15;
                uint32_t* d = W1 + row * 68 + c4 * 4;
                d[0] = f2tf(fw[e].x); d[1] = f2tf(fw[e].y);
                d[2] = f2tf(fw[e].z); d[3] = f2tf(fw[e].w);
            }
        }
        __syncthreads();
    }
#pragma unroll
    for (int mt = 0; mt < 4; ++mt) {
#pragma unroll
        for (int nt = 0; nt < 2; ++nt) {
            int brow = mt * 16 + gid;
            int m = m0 + wid * 16 + nt * 8 + 2 * tig;
            float* base0 = &g_part[((size_t)ks * BATCH + brow) * NLIN + m];
            float* base1 = &g_part[((size_t)ks * BATCH + brow + 8) * NLIN + m];
            *(float2*)base0 = make_float2(acc[mt][nt][0], acc[mt][nt][1]);
            *(float2*)base1 = make_float2(acc[mt][nt][2], acc[mt][nt][3]);
        }
    }
}

// ---------------- tensor-core LSTM recurrence v2 ----------------
// 64 blocks x 256 threads; block owns 8 h-cols (32 gate rows). W frags hi/lo
// (128 KB) resident in smem. h circulates as pre-split hi/lo u32 arrays
// (producer-side conversion). K staged in 4 chunks of 128 with reg prefetch.
// Warp = (mg 0..3, kh 0..1); kh halves reduced through smem.
__device__ __forceinline__ void lstm_mma(
    const float* __restrict__ Whh,
    const float* __restrict__ pre, int preStride,
    uint32_t* __restrict__ hAhi, uint32_t* __restrict__ hAlo, float* __restrict__ hAf,
    uint32_t* __restrict__ hBhi, uint32_t* __restrict__ hBlo, float* __restrict__ hBf,
    float* __restrict__ cbuf, int loadC, int saveC,
    float* __restrict__ seqOut, int nsteps)
{
    extern __shared__ __align__(16) uint32_t sm[];
    uint32_t* wsf = sm;
    uint32_t* Ahi = sm + AHI_OFF;
    uint32_t* Alo = sm + ALO_OFF;
    float* Csm = (float*)(sm + CSM_OFF);
    float* red = (float*)(sm + RED_OFF);

    const int tid = threadIdx.x;
    const int bk = blockIdx.x;
    const int hc0 = bk * 8;
    const int lane = tid & 31, wid = tid >> 5;
    const int mg = wid & 3, kh = wid >> 2;
    const int gid = lane >> 2, tig = lane & 3;
    const int eb = tid >> 2, ec = tid & 3;   // epilogue: batch row, col pair

    // one-time W frag build: fragId=(ktg*4+nt)*2+term, 64 u32 each (lane*2+rg)
    for (int idx = tid; idx < 32768; idx += 256) {
        int fragId = idx >> 6, rem = idx & 63;
        int ln = rem >> 1, rg = rem & 1;
        int ktg = fragId >> 3, nt = (fragId >> 1) & 3, term = fragId & 1;
        int g2 = ln >> 2, t2 = ln & 3;
        int r = nt * 8 + g2;
        int q = r >> 3, cc = r & 7;
        int k = ktg * 8 + t2 + 4 * rg;
        float w = Whh[(size_t)(q * HID + hc0 + cc) * HID + k];
        uint32_t hi = f2tf(w);
        wsf[idx] = (term == 0) ? hi : f2tf(w - __uint_as_float(hi));
    }
    __syncthreads();

    float2 creg = make_float2(0.f, 0.f);
    if (loadC) creg = *(const float2*)&cbuf[eb * HID + hc0 + ec * 2];

    for (int t = 0; t < nsteps; ++t) {
        const uint32_t* hinHi = (t & 1) ? hBhi : hAhi;
        const uint32_t* hinLo = (t & 1) ? hBlo : hAlo;
        uint32_t* houtHi = (t & 1) ? hAhi : hBhi;
        uint32_t* houtLo = (t & 1) ? hAlo : hBlo;
        float* houtF = (t & 1) ? hAf : hBf;

        float2 pr[4];
        {
            const float* pp = pre + (size_t)t * preStride + eb * G4 + hc0 + ec * 2;
#pragma unroll
            for (int q = 0; q < 4; ++q)
                pr[q] = __ldg((const float2*)(pp + q * 512));
        }

        float acc[4][4];
#pragma unroll
        for (int nt = 0; nt < 4; ++nt)
#pragma unroll
            for (int r = 0; r < 4; ++r) acc[nt][r] = 0.f;

        uint4 vh[8], vl[8];
#pragma unroll
        for (int e = 0; e < 8; ++e) {
            int idx = tid + e * 256, row = idx >> 5, f4 = idx & 31;
            vh[e] = __ldcg((const uint4*)(hinHi + row * 512 + f4 * 4));
            vl[e] = __ldcg((const uint4*)(hinLo + row * 512 + f4 * 4));
        }

#pragma unroll 1
        for (int ck = 0; ck < 4; ++ck) {
#pragma unroll
            for (int e = 0; e < 8; ++e) {
                int idx = tid + e * 256, row = idx >> 5, f4 = idx & 31;
                *(uint4*)(Ahi + row * AP + f4 * 4) = vh[e];
                *(uint4*)(Alo + row * AP + f4 * 4) = vl[e];
            }
            if (ck < 3) {
                int ko = (ck + 1) * 128;
#pragma unroll
                for (int e = 0; e < 8; ++e) {
                    int idx = tid + e * 256, row = idx >> 5, f4 = idx & 31;
                    vh[e] = __ldcg((const uint4*)(hinHi + row * 512 + ko + f4 * 4));
                    vl[e] = __ldcg((const uint4*)(hinLo + row * 512 + ko + f4 * 4));
                }
            }
            __syncthreads();
#pragma unroll
            for (int ki = 0; ki < 8; ++ki) {
                int ktc = kh * 8 + ki;
                int ktg = ck * 16 + ktc;
                int abase = (mg * 16 + gid) * AP + ktc * 8 + tig;
                uint32_t ah[4], al[4];
                ah[0] = Ahi[abase];          ah[1] = Ahi[abase + 8 * AP];
                ah[2] = Ahi[abase + 4];      ah[3] = Ahi[abase + 8 * AP + 4];
                al[0] = Alo[abase];          al[1] = Alo[abase + 8 * AP];
                al[2] = Alo[abase + 4];      al[3] = Alo[abase + 8 * AP + 4];
#pragma unroll
                for (int nt = 0; nt < 4; ++nt) {
                    int fb = ((ktg * 4 + nt) * 2) * 64 + lane * 2;
                    uint32_t bh[2], bl[2];
                    *(uint2*)bh = *(const uint2*)(wsf + fb);
                    *(uint2*)bl = *(const uint2*)(wsf + fb + 64);
                    mma_tf32(acc[nt], ah, bh);
                    mma_tf32(acc[nt], ah, bl);
                    mma_tf32(acc[nt], al, bh);
                }
            }
            __syncthreads();
        }

        if (kh == 1) {
#pragma unroll
            for (int nt = 0; nt < 4; ++nt)
                *(float4*)(red + ((mg * 32 + lane) * 4 + nt) * 4) =
                    make_float4(acc[nt][0], acc[nt][1], acc[nt][2], acc[nt][3]);
        }
        __syncthreads();
        if (kh == 0) {
#pragma unroll
            for (int nt = 0; nt < 4; ++nt) {
                float4 r4 = *(const float4*)(red + ((mg * 32 + lane) * 4 + nt) * 4);
                int row = mg * 16 + gid, col = nt * 8 + 2 * tig;
                Csm[row * 36 + col]           = acc[nt][0] + r4.x;
                Csm[row * 36 + col + 1]       = acc[nt][1] + r4.y;
                Csm[(row + 8) * 36 + col]     = acc[nt][2] + r4.z;
                Csm[(row + 8) * 36 + col + 1] = acc[nt][3] + r4.w;
            }
        }
        __syncthreads();

        // epilogue: thread handles (eb, cc=ec*2, ec*2+1); gate q at col q*8+cc
        {
            const float* cb = Csm + eb * 36 + ec * 2;
            float2 a0 = *(const float2*)(cb);
            float2 a1 = *(const float2*)(cb + 8);
            float2 a2 = *(const float2*)(cb + 16);
            float2 a3 = *(const float2*)(cb + 24);
            a0.x += pr[0].x; a0.y += pr[0].y;
            a1.x += pr[1].x; a1.y += pr[1].y;
            a2.x += pr[2].x; a2.y += pr[2].y;
            a3.x += pr[3].x; a3.y += pr[3].y;
            float si0 = 1.f / (1.f + __expf(-a0.x)), si1 = 1.f / (1.f + __expf(-a0.y));
            float sf0 = 1.f / (1.f + __expf(-a1.x)), sf1 = 1.f / (1.f + __expf(-a1.y));
            float so0 = 1.f / (1.f + __expf(-a3.x)), so1 = 1.f / (1.f + __expf(-a3.y));
            creg.x = sf0 * creg.x + si0 * tanhf(a2.x);
            creg.y = sf1 * creg.y + si1 * tanhf(a2.y);
            float h0 = so0 * tanhf(creg.x);
            float h1 = so1 * tanhf(creg.y);
            uint32_t hh0 = f2tf(h0), hh1 = f2tf(h1);
            int off = eb * 512 + hc0 + ec * 2;
            *(uint2*)(houtHi + off) = make_uint2(hh0, hh1);
            *(uint2*)(houtLo + off) = make_uint2(
                f2tf(h0 - __uint_as_float(hh0)), f2tf(h1 - __uint_as_float(hh1)));
            *(float2*)(houtF + off) = make_float2(h0, h1);
            if (seqOut)
                *(float2*)(&seqOut[(size_t)eb * KLIN + t * 512 + hc0 + ec * 2]) =
                    make_float2(h0, h1);
        }
        __syncthreads();

        if (t + 1 < nsteps) {
            if (tid == 0) {
                __threadfence();
                atomicAdd(&g_ctr[bk & 7], 1u);
                unsigned need = 8u * (unsigned)(t + 1);
                for (;;) {
                    bool ok = true;
#pragma unroll
                    for (int i = 0; i < 8; ++i)
                        if (*(volatile unsigned*)&g_ctr[i] < need) { ok = false; break; }
                    if (ok) break;
                    __nanosleep(32);
                }
                __threadfence();
            }
            __syncthreads();
        }
    }
    if (saveC) *(float2*)&cbuf[eb * HID + hc0 + ec * 2] = creg;
}

__global__ void __launch_bounds__(256, 1) k_enc(const float* __restrict__ Whh) {
    lstm_mma(Whh, g_pre1, BATCH * G4, g_hAhi, g_hAlo, g_hA,
             g_hBhi, g_hBlo, g_hB, g_c, 0, 1, nullptr, TIN);
}
__global__ void __launch_bounds__(256, 1) k_dec(const float* __restrict__ Whh) {
    lstm_mma(Whh, g_pre2, 0, g_hAhi, g_hAlo, g_hA,
             g_hBhi, g_hBlo, g_hB, g_c, 1, 0, g_seq, TOUTN);
}

extern "C" void kernel_launch(void* const* d_in, const int* in_sizes, int n_in,
                              void* d_out, int out_size) {
    const float* x    = (const float*)d_in[0];
    const float* Wih1 = (const float*)d_in[1];
    const float* Whh1 = (const float*)d_in[2];
    const float* bih1 = (const float*)d_in[3];
    const float* bhh1 = (const float*)d_in[4];
    const float* Wih2 = (const float*)d_in[5];
    const float* Whh2 = (const float*)d_in[6];
    const float* bih2 = (const float*)d_in[7];
    const float* bhh2 = (const float*)d_in[8];
    const float* Wlin = (const float*)d_in[9];
    const float* blin = (const float*)d_in[10];
    float* out = (float*)d_out;

    const int lstmSmem = DSMW * 4;        // 216064
    const int linSmem  = 2 * 13056 * 4;   // 104448
    cudaFuncSetAttribute(k_enc, cudaFuncAttributeMaxDynamicSharedMemorySize, lstmSmem);
    cudaFuncSetAttribute(k_dec, cudaFuncAttributeMaxDynamicSharedMemorySize, lstmSmem);
    cudaFuncSetAttribute(k_lin_mma, cudaFuncAttributeMaxDynamicSharedMemorySize, linSmem);

    k_xt<<<(TIN * BATCH * FIN + 255) / 256, 256>>>(x);
    k_init<<<(BATCH * HID + 255) / 256, 256>>>();

    dim3 gpre1(G4 / 64, 1, (TIN * BATCH) / 64);
    k_pre1<<<gpre1, 256>>>(Wih1, bih1, bhh1);

    k_enc<<<NBLK_L, 256, lstmSmem>>>(Whh1);   // TIN even: final h in A-set

    dim3 gpre2(G4 / 64, 1, 1);
    k_pre2<<<gpre2, 256>>>(Wih2, bih2, bhh2);

    k_zero<<<1, 32>>>();
    k_dec<<<NBLK_L, 256, lstmSmem>>>(Whh2);

    dim3 glin(NLIN / 128, KSPLIT);
    k_lin_mma<<<glin, 256, linSmem>>>(Wlin);

    k_combine<<<(BATCH * NLIN + 255) / 256, 256>>>(blin, out);
}